// round 10
// baseline (speedup 1.0000x reference)
#include <cuda_runtime.h>
#include <cuda_fp16.h>
#include <cstdint>

// Problem constants
#define Bsz   64
#define Tlen  256
#define INSZ  256
#define Hdim  64
#define Gdim  256        // 4*Hdim
#define Vocab 8000
#define Mrows (Bsz * Tlen)   // 16384

// Scratch (device globals; no allocation allowed in kernel_launch)
__device__ float g_xproj[Mrows * Gdim];
__device__ float g_h0[Mrows * Hdim];                    // layer0 output (fp32)
__device__ int   g_flag[Bsz];                           // per-batch progress flags
__device__ __align__(128) __half g_Ah[Mrows * Hdim];    // h2 (layer1 out) fp16
__device__ __align__(128) __half g_Bh[Vocab * Hdim];    // 8*Wl fp16

// ---------------- packed f32x2 helpers ----------------
__device__ __forceinline__ unsigned long long pack2(float x) {
    unsigned long long r;
    asm("mov.b64 %0, {%1, %1};" : "=l"(r) : "f"(x));
    return r;
}
__device__ __forceinline__ unsigned long long pack2v(float x, float y) {
    unsigned long long r;
    asm("mov.b64 %0, {%1, %2};" : "=l"(r) : "f"(x), "f"(y));
    return r;
}
__device__ __forceinline__ void fma2(unsigned long long& d, unsigned long long a,
                                     unsigned long long b) {
    asm("fma.rn.f32x2 %0, %1, %2, %0;" : "+l"(d) : "l"(a), "l"(b));
}
__device__ __forceinline__ float2 unpack2(unsigned long long v) {
    float2 f;
    asm("mov.b64 {%0, %1}, %2;" : "=f"(f.x), "=f"(f.y) : "l"(v));
    return f;
}
__device__ __forceinline__ float fast_rcp(float x) {
    float r;
    asm("rcp.approx.f32 %0, %1;" : "=f"(r) : "f"(x));
    return r;
}
__device__ __forceinline__ float sigmoidf_(float x) {
    return fast_rcp(1.0f + __expf(-x));
}
__device__ __forceinline__ float tanh_fast(float x) {
    return 1.0f - 2.0f * fast_rcp(1.0f + __expf(2.0f * x));
}
// 64-long dot: wp = 32 packed f32x2, h = 64 floats (8B-aligned SMEM)
__device__ __forceinline__ float dot64(const unsigned long long* wp, const float* h) {
    const unsigned long long* hp = reinterpret_cast<const unsigned long long*>(h);
    unsigned long long a0 = 0ULL, a1 = 0ULL, a2 = 0ULL, a3 = 0ULL;
#pragma unroll
    for (int j = 0; j < 32; j += 4) {
        fma2(a0, wp[j + 0], hp[j + 0]);
        fma2(a1, wp[j + 1], hp[j + 1]);
        fma2(a2, wp[j + 2], hp[j + 2]);
        fma2(a3, wp[j + 3], hp[j + 3]);
    }
    float2 s0 = unpack2(a0), s1 = unpack2(a1), s2 = unpack2(a2), s3 = unpack2(a3);
    return (((s0.x + s0.y) + (s1.x + s1.y)) + ((s2.x + s2.y) + (s3.x + s3.y)));
}
__device__ __forceinline__ void wait_flag(const int* f, int want) {
    int v;
    do {
        asm volatile("ld.acquire.gpu.global.u32 %0, [%1];"
                     : "=r"(v) : "l"(f) : "memory");
    } while (v < want);
}

// ---------------- generic C[M,N] = A[M,K] * B[N,K]^T + bias1 (+bias2) ----------------
__global__ void gemm_nt_bias(const float* __restrict__ A, const float* __restrict__ Bm,
                             const float* __restrict__ bias1, const float* __restrict__ bias2,
                             float* __restrict__ C, int M, int N, int K)
{
    __shared__ __align__(16) float As[64][17];
    __shared__ __align__(16) float Bs[16][68];

    const int t  = threadIdx.x;
    const int bm = blockIdx.y * 64;
    const int bn = blockIdx.x * 64;
    const int tm = (t >> 4) << 2;
    const int tn = (t & 15) << 2;
    const int lr = t >> 2;
    const int lk = (t & 3) << 2;

    unsigned long long acc[4][2];
#pragma unroll
    for (int i = 0; i < 4; i++) { acc[i][0] = 0ULL; acc[i][1] = 0ULL; }

    const float* Aptr = A  + (size_t)(bm + lr) * K + lk;
    const float* Bptr = Bm + (size_t)(bn + lr) * K + lk;

    for (int k0 = 0; k0 < K; k0 += 16) {
        float4 av = *reinterpret_cast<const float4*>(Aptr + k0);
        float4 bv = *reinterpret_cast<const float4*>(Bptr + k0);
        As[lr][lk + 0] = av.x; As[lr][lk + 1] = av.y;
        As[lr][lk + 2] = av.z; As[lr][lk + 3] = av.w;
        Bs[lk + 0][lr] = bv.x; Bs[lk + 1][lr] = bv.y;
        Bs[lk + 2][lr] = bv.z; Bs[lk + 3][lr] = bv.w;
        __syncthreads();
#pragma unroll
        for (int kk = 0; kk < 16; kk++) {
            unsigned long long b0 =
                *reinterpret_cast<const unsigned long long*>(&Bs[kk][tn]);
            unsigned long long b1 =
                *reinterpret_cast<const unsigned long long*>(&Bs[kk][tn + 2]);
#pragma unroll
            for (int i = 0; i < 4; i++) {
                unsigned long long ap = pack2(As[tm + i][kk]);
                fma2(acc[i][0], ap, b0);
                fma2(acc[i][1], ap, b1);
            }
        }
        __syncthreads();
    }

    float4 bvec;
    bvec.x = bias1[bn + tn + 0];
    bvec.y = bias1[bn + tn + 1];
    bvec.z = bias1[bn + tn + 2];
    bvec.w = bias1[bn + tn + 3];
    if (bias2) {
        bvec.x += bias2[bn + tn + 0];
        bvec.y += bias2[bn + tn + 1];
        bvec.z += bias2[bn + tn + 2];
        bvec.w += bias2[bn + tn + 3];
    }
#pragma unroll
    for (int i = 0; i < 4; i++) {
        float2 lo = unpack2(acc[i][0]);
        float2 hi = unpack2(acc[i][1]);
        float4 v = make_float4(lo.x + bvec.x, lo.y + bvec.y,
                               hi.x + bvec.z, hi.y + bvec.w);
        *reinterpret_cast<float4*>(&C[(size_t)(bm + tm + i) * N + bn + tn]) = v;
    }
}

// ---------------- flag reset (runs before lstm_dual each replay) ----------------
__global__ void reset_flags()
{
    g_flag[threadIdx.x] = 0;
}

// ============ Dual-layer LSTM: producer/consumer CTAs, per-step flags ===============
// CTAs 0..63   : layer0 for batch b = cta  (256 active threads, R9 quad-shuffle form).
//                Publishes h0[b][t] to global + release flag[b]=t+1 per step.
// CTAs 64..127 : layer1 for batch b = cta-64 (512 threads):
//                G0 (0-255):  pih[g] = W_ih1[g] @ h0[t]  (loaders poll flag, 2-step lag)
//                G1 (256-511): gates for step t-1 = pih + W_hh1 @ h1[t-2] + biases.
//                Writes h1 directly as fp16 (logits A operand).
__global__ void __launch_bounds__(512, 1)
lstm_dual(const float* __restrict__ xproj,   // [B,T,256] layer0 proj incl. biases
          const float* __restrict__ Whh0,    // [256,64]
          const float* __restrict__ Wih1,    // [256,64]
          const float* __restrict__ Whh1,    // [256,64]
          const float* __restrict__ bih1,    // [256]
          const float* __restrict__ bhh1,    // [256]
          float* __restrict__ h0g,           // [B,T,64] fp32 (cross-CTA)
          __half* __restrict__ ah_out)       // [B,T,64] fp16
{
    const int cta = blockIdx.x;

    if (cta < Bsz) {
        // ------------------------------ layer 0 ------------------------------
        if (threadIdx.x >= 256) return;     // exited threads don't join barriers
        __shared__ __align__(16) float h_sh[2][Hdim];

        const int b = cta;
        const int tid = threadIdx.x;
        const int q = tid >> 2;
        const int k = tid & 3;
        const int base = (tid & 31) & ~3;
        const int gidx = k * Hdim + q;

        unsigned long long wp[Hdim / 2];
#pragma unroll
        for (int j = 0; j < Hdim / 2; j++) {
            float2 v = *reinterpret_cast<const float2*>(Whh0 + gidx * Hdim + 2 * j);
            wp[j] = pack2v(v.x, v.y);
        }

        if (tid < Hdim) { h_sh[0][tid] = 0.0f; h_sh[1][tid] = 0.0f; }
        __syncthreads();

        const float* xp = xproj + (size_t)b * Tlen * Gdim;
        float xcur = xp[gidx];
        float c = 0.0f;

        for (int t = 0; t < Tlen; t++) {
            float xnext = (t + 1 < Tlen) ? xp[(size_t)(t + 1) * Gdim + gidx] : 0.0f;
            float val = xcur + dot64(wp, h_sh[t & 1]);
            xcur = xnext;

            float act = (k == 2) ? tanh_fast(val) : sigmoidf_(val);
            float iv = __shfl_sync(0xffffffffu, act, base + 0);
            float fv = __shfl_sync(0xffffffffu, act, base + 1);
            float gv = __shfl_sync(0xffffffffu, act, base + 2);
            float ov = __shfl_sync(0xffffffffu, act, base + 3);

            c = fv * c + iv * gv;
            float hn = ov * tanh_fast(c);

            if (k == 0) {
                h_sh[(t + 1) & 1][q] = hn;
                h0g[((size_t)b * Tlen + t) * Hdim + q] = hn;
                __threadfence();            // make h0 row globally visible
            }
            __syncthreads();
            if (tid == 0) {                 // publish progress (release)
                asm volatile("st.release.gpu.global.u32 [%0], %1;"
                             :: "l"(&g_flag[b]), "r"(t + 1) : "memory");
            }
        }
    } else {
        // ------------------------------ layer 1 ------------------------------
        __shared__ __align__(16) float h0s[2][Hdim];
        __shared__ __align__(16) float h1s[2][Hdim];
        __shared__ float pih_s[2][Gdim];

        const int b = cta - Bsz;
        const int tid = threadIdx.x;
        const int grp = tid >> 8;           // 0 = pih, 1 = gates
        const int l = tid & 255;

        // weight row (register-resident)
        const int gidx = (grp == 0) ? l : ((l & 3) * Hdim + (l >> 2));
        const float* wsrc = (grp == 0) ? (Wih1 + (size_t)gidx * Hdim)
                                       : (Whh1 + (size_t)gidx * Hdim);
        unsigned long long wp[Hdim / 2];
#pragma unroll
        for (int j = 0; j < Hdim / 2; j++) {
            float2 v = *reinterpret_cast<const float2*>(wsrc + 2 * j);
            wp[j] = pack2v(v.x, v.y);
        }

        int q = 0, k = 0, base = 0;
        float bias = 0.0f;
        if (grp == 1) {
            q = l >> 2; k = l & 3;
            base = (tid & 31) & ~3;
            bias = bih1[gidx] + bhh1[gidx];
        }

        if (tid < Hdim) { h1s[0][tid] = 0.0f; h1s[1][tid] = 0.0f; }

        // preload h0[0] (loaders: G0 threads 0..63)
        if (grp == 0 && l < Hdim) {
            wait_flag(&g_flag[b], 1);
            h0s[0][l] = h0g[((size_t)b * Tlen + 0) * Hdim + l];
        }
        __syncthreads();

        float c = 0.0f;
        const float* h0row = h0g + (size_t)b * Tlen * Hdim;

        for (int i = 0; i <= Tlen; i++) {
            if (grp == 0) {
                if (l < Hdim && i + 1 < Tlen) {      // load h0[i+1] for next iter
                    wait_flag(&g_flag[b], i + 2);
                    h0s[(i + 1) & 1][l] = h0row[(size_t)(i + 1) * Hdim + l];
                }
                if (i < Tlen)                        // pih for step i from h0[i]
                    pih_s[i & 1][l] = dot64(wp, h0s[i & 1]);
            } else {
                if (i >= 1) {                        // gates for step s = i-1
                    const int s = i - 1;
                    float val = bias + pih_s[s & 1][gidx] + dot64(wp, h1s[i & 1]);
                    float act = (k == 2) ? tanh_fast(val) : sigmoidf_(val);
                    float iv = __shfl_sync(0xffffffffu, act, base + 0);
                    float fv = __shfl_sync(0xffffffffu, act, base + 1);
                    float gv = __shfl_sync(0xffffffffu, act, base + 2);
                    float ov = __shfl_sync(0xffffffffu, act, base + 3);
                    c = fv * c + iv * gv;
                    float hn = ov * tanh_fast(c);
                    if (k == 0) {
                        h1s[s & 1][q] = hn;
                        ah_out[((size_t)b * Tlen + s) * Hdim + q] = __float2half(hn);
                    }
                }
            }
            __syncthreads();
        }
    }
}

// ---------------- Wl -> fp16 (scaled by 8 for fp16 normal range) -------
__global__ void cvt_bh(const float* __restrict__ in, __half* __restrict__ out, int n)
{
    int i = blockIdx.x * blockDim.x + threadIdx.x;
    if (i < n) out[i] = __float2half(in[i] * 8.0f);
}

// ============ HMMA fp16 logits GEMM (byte-identical to passing R7) ==================
#define SWZ128(off) ((off) ^ (((off) >> 3) & 0x70))
#define LS_B    0
#define LS_A    8192
#define LS_ASTG 16384
#define LG_SMEM (8192 + 2 * 16384 + 1024)
#define NM_TILES 8

static __device__ __forceinline__ uint32_t smem_u32(const void* p) {
    uint32_t a;
    asm("{ .reg .u64 t; cvta.to.shared.u64 t, %1; cvt.u32.u64 %0, t; }"
        : "=r"(a) : "l"(p));
    return a;
}
__device__ __forceinline__ void cp16(uint32_t dst, const void* src) {
    asm volatile("cp.async.cg.shared.global [%0], [%1], 16;"
                 :: "r"(dst), "l"(src));
}
__device__ __forceinline__ void cp_commit() {
    asm volatile("cp.async.commit_group;" ::: "memory");
}
template <int N>
__device__ __forceinline__ void cp_wait() {
    asm volatile("cp.async.wait_group %0;" :: "n"(N) : "memory");
}
__device__ __forceinline__ void ldsm_x4(uint32_t& r0, uint32_t& r1, uint32_t& r2,
                                        uint32_t& r3, uint32_t addr) {
    asm volatile("ldmatrix.sync.aligned.m8n8.x4.shared.b16 {%0,%1,%2,%3}, [%4];"
                 : "=r"(r0), "=r"(r1), "=r"(r2), "=r"(r3) : "r"(addr));
}
__device__ __forceinline__ void mma_f16(float* c, uint32_t a0, uint32_t a1,
                                        uint32_t a2, uint32_t a3,
                                        uint32_t b0, uint32_t b1) {
    asm volatile("mma.sync.aligned.m16n8k16.row.col.f32.f16.f16.f32 "
                 "{%0,%1,%2,%3}, {%4,%5,%6,%7}, {%8,%9}, {%0,%1,%2,%3};"
                 : "+f"(c[0]), "+f"(c[1]), "+f"(c[2]), "+f"(c[3])
                 : "r"(a0), "r"(a1), "r"(a2), "r"(a3), "r"(b0), "r"(b1));
}
__device__ __forceinline__ void stg_cs_f2(float* p, float x, float y) {
    asm volatile("st.global.cs.v2.f32 [%0], {%1,%2};" :: "l"(p), "f"(x), "f"(y));
}

__device__ __forceinline__ void load_A_stage(uint32_t sA, const __half* Ah,
                                             int bm, int tid) {
    const int row = tid >> 1;
    const int cb = (tid & 1) * 4;
    const char* src = reinterpret_cast<const char*>(Ah + (size_t)(bm + row) * Hdim);
#pragma unroll
    for (int i = 0; i < 4; i++) {
        uint32_t off = SWZ128((uint32_t)(row * 128 + (cb + i) * 16));
        cp16(sA + off, src + (cb + i) * 16);
    }
}

__global__ void __launch_bounds__(256)
logits_gemm(const __half* __restrict__ Ah, const __half* __restrict__ Bh,
            const float* __restrict__ bias, float* __restrict__ C)
{
    extern __shared__ char smem_raw[];
    const uint32_t sb0 = smem_u32(smem_raw);
    const uint32_t sb = (sb0 + 1023) & ~1023u;

    const int tid = threadIdx.x;
    const int lane = tid & 31;
    const int wid = tid >> 5;
    const int wm = wid & 3;
    const int wn = wid >> 2;
    const int bn = blockIdx.x * 64;
    const int bm0 = blockIdx.y * (NM_TILES * 128);

    {
        const int row = tid >> 2;
        const int cb = (tid & 3) * 2;
        const char* src = reinterpret_cast<const char*>(Bh + (size_t)(bn + row) * Hdim);
#pragma unroll
        for (int i = 0; i < 2; i++) {
            uint32_t off = SWZ128((uint32_t)(row * 128 + (cb + i) * 16));
            cp16(sb + LS_B + off, src + (cb + i) * 16);
        }
    }
    load_A_stage(sb + LS_A, Ah, bm0, tid);
    cp_commit();

    const int gid = lane >> 2;
    const int tig = lane & 3;
    float2 bv[4];
#pragma unroll
    for (int nt = 0; nt < 4; nt++)
        bv[nt] = *reinterpret_cast<const float2*>(bias + bn + wn * 32 + nt * 8 + 2 * tig);

    const int rsel = lane & 15;
    const int csel = lane >> 4;

    for (int it = 0; it < NM_TILES; it++) {
        const uint32_t sA = sb + LS_A + (it & 1) * LS_ASTG;
        if (it + 1 < NM_TILES) {
            load_A_stage(sb + LS_A + ((it + 1) & 1) * LS_ASTG, Ah,
                         bm0 + (it + 1) * 128, tid);
            cp_commit();
            cp_wait<1>();
        } else {
            cp_wait<0>();
        }
        __syncthreads();

        float acc[2][4][4];
#pragma unroll
        for (int i = 0; i < 2; i++)
#pragma unroll
            for (int j = 0; j < 4; j++)
#pragma unroll
                for (int q = 0; q < 4; q++) acc[i][j][q] = 0.0f;

#pragma unroll
        for (int ks = 0; ks < 4; ks++) {
            const int col16 = ks * 2 + csel;
            uint32_t a[2][4];
#pragma unroll
            for (int mt = 0; mt < 2; mt++) {
                int row = wm * 32 + mt * 16 + rsel;
                uint32_t addr = sA + SWZ128((uint32_t)(row * 128 + col16 * 16));
                ldsm_x4(a[mt][0], a[mt][1], a[mt][2], a[mt][3], addr);
            }
            uint32_t b0[4], b1[4];
#pragma unroll
            for (int np = 0; np < 2; np++) {
                int row = wn * 32 + np * 16 + rsel;
                uint32_t addr = sb + LS_B + SWZ128((uint32_t)(row * 128 + col16 * 16));
                uint32_t r0, r1, r2, r3;
                ldsm_x4(r0, r1, r2, r3, addr);
                b0[np * 2 + 0] = r0; b0[np * 2 + 1] = r1;
                b1[np * 2 + 0] = r2; b1[np * 2 + 1] = r3;
            }
#pragma unroll
            for (int mt = 0; mt < 2; mt++)
#pragma unroll
                for (int nt = 0; nt < 4; nt++)
                    mma_f16(acc[mt][nt], a[mt][0], a[mt][1], a[mt][2], a[mt][3],
                            b0[nt], b1[nt]);
        }

        const int bm = bm0 + it * 128;
#pragma unroll
        for (int nt = 0; nt < 4; nt++) {
            const int gn = bn + wn * 32 + nt * 8 + 2 * tig;
#pragma unroll
            for (int mt = 0; mt < 2; mt++) {
                const int gm0 = bm + wm * 32 + mt * 16 + gid;
                float x0 = fmaf(acc[mt][nt][0], 0.125f, bv[nt].x);
                float y0 = fmaf(acc[mt][nt][1], 0.125f, bv[nt].y);
                float x1 = fmaf(acc[mt][nt][2], 0.125f, bv[nt].x);
                float y1 = fmaf(acc[mt][nt][3], 0.125f, bv[nt].y);
                stg_cs_f2(C + (size_t)gm0 * Vocab + gn, x0, y0);
                stg_cs_f2(C + (size_t)(gm0 + 8) * Vocab + gn, x1, y1);
            }
        }
        __syncthreads();
    }
}

// ------------------------------------ launch --------------------------------------
extern "C" void kernel_launch(void* const* d_in, const int* in_sizes, int n_in,
                              void* d_out, int out_size)
{
    (void)in_sizes; (void)n_in; (void)out_size;
    const float* x     = (const float*)d_in[0];
    const float* W_ih0 = (const float*)d_in[1];
    const float* W_hh0 = (const float*)d_in[2];
    const float* b_ih0 = (const float*)d_in[3];
    const float* b_hh0 = (const float*)d_in[4];
    const float* W_ih1 = (const float*)d_in[5];
    const float* W_hh1 = (const float*)d_in[6];
    const float* b_ih1 = (const float*)d_in[7];
    const float* b_hh1 = (const float*)d_in[8];
    const float* Wl    = (const float*)d_in[9];
    const float* bl    = (const float*)d_in[10];
    float* out = (float*)d_out;

    void* p;
    cudaGetSymbolAddress(&p, g_xproj); float* xproj = (float*)p;
    cudaGetSymbolAddress(&p, g_h0);    float* h0g   = (float*)p;
    cudaGetSymbolAddress(&p, g_Ah);    __half* Ah   = (__half*)p;
    cudaGetSymbolAddress(&p, g_Bh);    __half* Bh   = (__half*)p;

    // flag reset must precede lstm_dual on every replay
    reset_flags<<<1, Bsz>>>();

    // Wl -> fp16 (independent of LSTM chain)
    cvt_bh<<<(Vocab * Hdim + 255) / 256, 256>>>(Wl, Bh, Vocab * Hdim);

    // Layer 0 input projection (biases folded in)
    gemm_nt_bias<<<dim3(Gdim / 64, Mrows / 64), 256>>>(
        x, W_ih0, b_ih0, b_hh0, xproj, Mrows, Gdim, INSZ);

    // Both recurrences, cross-CTA pipelined (proj1 folded into layer1 CTAs)
    lstm_dual<<<2 * Bsz, 512>>>(xproj, W_hh0, W_ih1, W_hh1, b_ih1, b_hh1, h0g, Ah);

    // Logits via pipelined HMMA fp16 single pass
    cudaFuncSetAttribute(logits_gemm, cudaFuncAttributeMaxDynamicSharedMemorySize, LG_SMEM);
    logits_gemm<<<dim3(Vocab / 64, Mrows / (NM_TILES * 128)), 256, LG_SMEM>>>(
        Ah, Bh, bl, out);
}

// round 11
// speedup vs baseline: 1.0596x; 1.0596x over previous
#include <cuda_runtime.h>
#include <cuda_fp16.h>
#include <cstdint>

// Problem constants
#define Bsz   64
#define Tlen  256
#define INSZ  256
#define Hdim  64
#define Gdim  256        // 4*Hdim
#define Vocab 8000
#define Mrows (Bsz * Tlen)   // 16384

// Scratch (device globals; no allocation allowed in kernel_launch)
__device__ float g_xproj[Mrows * Gdim];
__device__ float g_h0[Mrows * Hdim];                    // layer0 output (fp32)
__device__ int   g_flag[Bsz * 32];                      // per-batch flags, 128B stride
__device__ __align__(128) __half g_Ah[Mrows * Hdim];    // h2 (layer1 out) fp16
__device__ __align__(128) __half g_Bh[Vocab * Hdim];    // 8*Wl fp16

// ---------------- packed f32x2 helpers ----------------
__device__ __forceinline__ unsigned long long pack2(float x) {
    unsigned long long r;
    asm("mov.b64 %0, {%1, %1};" : "=l"(r) : "f"(x));
    return r;
}
__device__ __forceinline__ unsigned long long pack2v(float x, float y) {
    unsigned long long r;
    asm("mov.b64 %0, {%1, %2};" : "=l"(r) : "f"(x), "f"(y));
    return r;
}
__device__ __forceinline__ void fma2(unsigned long long& d, unsigned long long a,
                                     unsigned long long b) {
    asm("fma.rn.f32x2 %0, %1, %2, %0;" : "+l"(d) : "l"(a), "l"(b));
}
__device__ __forceinline__ float2 unpack2(unsigned long long v) {
    float2 f;
    asm("mov.b64 {%0, %1}, %2;" : "=f"(f.x), "=f"(f.y) : "l"(v));
    return f;
}
__device__ __forceinline__ float fast_rcp(float x) {
    float r;
    asm("rcp.approx.f32 %0, %1;" : "=f"(r) : "f"(x));
    return r;
}
__device__ __forceinline__ float sigmoidf_(float x) {
    return fast_rcp(1.0f + __expf(-x));
}
__device__ __forceinline__ float tanh_fast(float x) {
    return 1.0f - 2.0f * fast_rcp(1.0f + __expf(2.0f * x));
}
// 64-long dot: wp = 32 packed f32x2, h = 64 floats (8B-aligned SMEM)
__device__ __forceinline__ float dot64(const unsigned long long* wp, const float* h) {
    const unsigned long long* hp = reinterpret_cast<const unsigned long long*>(h);
    unsigned long long a0 = 0ULL, a1 = 0ULL, a2 = 0ULL, a3 = 0ULL;
#pragma unroll
    for (int j = 0; j < 32; j += 4) {
        fma2(a0, wp[j + 0], hp[j + 0]);
        fma2(a1, wp[j + 1], hp[j + 1]);
        fma2(a2, wp[j + 2], hp[j + 2]);
        fma2(a3, wp[j + 3], hp[j + 3]);
    }
    float2 s0 = unpack2(a0), s1 = unpack2(a1), s2 = unpack2(a2), s3 = unpack2(a3);
    return (((s0.x + s0.y) + (s1.x + s1.y)) + ((s2.x + s2.y) + (s3.x + s3.y)));
}
__device__ __forceinline__ void wait_flag(const int* f, int want) {
    int v;
    do {
        asm volatile("ld.acquire.gpu.global.u32 %0, [%1];"
                     : "=r"(v) : "l"(f) : "memory");
    } while (v < want);
}

// ---------------- generic C[M,N] = A[M,K] * B[N,K]^T + bias1 (+bias2) ----------------
__global__ void gemm_nt_bias(const float* __restrict__ A, const float* __restrict__ Bm,
                             const float* __restrict__ bias1, const float* __restrict__ bias2,
                             float* __restrict__ C, int M, int N, int K)
{
    __shared__ __align__(16) float As[64][17];
    __shared__ __align__(16) float Bs[16][68];

    const int t  = threadIdx.x;
    const int bm = blockIdx.y * 64;
    const int bn = blockIdx.x * 64;
    const int tm = (t >> 4) << 2;
    const int tn = (t & 15) << 2;
    const int lr = t >> 2;
    const int lk = (t & 3) << 2;

    unsigned long long acc[4][2];
#pragma unroll
    for (int i = 0; i < 4; i++) { acc[i][0] = 0ULL; acc[i][1] = 0ULL; }

    const float* Aptr = A  + (size_t)(bm + lr) * K + lk;
    const float* Bptr = Bm + (size_t)(bn + lr) * K + lk;

    for (int k0 = 0; k0 < K; k0 += 16) {
        float4 av = *reinterpret_cast<const float4*>(Aptr + k0);
        float4 bv = *reinterpret_cast<const float4*>(Bptr + k0);
        As[lr][lk + 0] = av.x; As[lr][lk + 1] = av.y;
        As[lr][lk + 2] = av.z; As[lr][lk + 3] = av.w;
        Bs[lk + 0][lr] = bv.x; Bs[lk + 1][lr] = bv.y;
        Bs[lk + 2][lr] = bv.z; Bs[lk + 3][lr] = bv.w;
        __syncthreads();
#pragma unroll
        for (int kk = 0; kk < 16; kk++) {
            unsigned long long b0 =
                *reinterpret_cast<const unsigned long long*>(&Bs[kk][tn]);
            unsigned long long b1 =
                *reinterpret_cast<const unsigned long long*>(&Bs[kk][tn + 2]);
#pragma unroll
            for (int i = 0; i < 4; i++) {
                unsigned long long ap = pack2(As[tm + i][kk]);
                fma2(acc[i][0], ap, b0);
                fma2(acc[i][1], ap, b1);
            }
        }
        __syncthreads();
    }

    float4 bvec;
    bvec.x = bias1[bn + tn + 0];
    bvec.y = bias1[bn + tn + 1];
    bvec.z = bias1[bn + tn + 2];
    bvec.w = bias1[bn + tn + 3];
    if (bias2) {
        bvec.x += bias2[bn + tn + 0];
        bvec.y += bias2[bn + tn + 1];
        bvec.z += bias2[bn + tn + 2];
        bvec.w += bias2[bn + tn + 3];
    }
#pragma unroll
    for (int i = 0; i < 4; i++) {
        float2 lo = unpack2(acc[i][0]);
        float2 hi = unpack2(acc[i][1]);
        float4 v = make_float4(lo.x + bvec.x, lo.y + bvec.y,
                               hi.x + bvec.z, hi.y + bvec.w);
        *reinterpret_cast<float4*>(&C[(size_t)(bm + tm + i) * N + bn + tn]) = v;
    }
}

// ---------------- flag reset (runs before lstm_chain each replay) ----------------
__global__ void reset_flags()
{
    g_flag[threadIdx.x * 32] = 0;
}

// ============ Both LSTM layers, chunk-pipelined across CTAs =========================
// CTAs 0..63   (producer): layer0 for batch b, R9 quad-shuffle form. Stores h0 rows
//              to global; every 16 steps publishes flag[b] = t+1 (release).
// CTAs 64..127 (consumer): layer1 for batch b. Each thread holds BOTH its W_ih1 and
//              W_hh1 rows in registers and computes val = bias + Wih1@h0[t] + Whh1@h1[t-1].
//              h0 rows prefetched 2 steps ahead (LDG->reg->STS), gated by chunk flags
//              (flags are multiples of 16, so "chunk of t+2 done" == flag >= t+3).
//              Writes h1 directly as fp16 (logits A operand).
__global__ void __launch_bounds__(256, 1)
lstm_chain(const float* __restrict__ xproj,   // [B,T,256] layer0 proj incl. biases
           const float* __restrict__ Whh0,    // [256,64]
           const float* __restrict__ Wih1,    // [256,64]
           const float* __restrict__ Whh1,    // [256,64]
           const float* __restrict__ bih1,    // [256]
           const float* __restrict__ bhh1,    // [256]
           float* __restrict__ h0g,           // [B,T,64] fp32 (cross-CTA)
           __half* __restrict__ ah_out)       // [B,T,64] fp16
{
    const int cta = blockIdx.x;
    const int tid = threadIdx.x;
    const int q = tid >> 2;          // h index 0..63
    const int k = tid & 3;           // gate type 0=i 1=f 2=g 3=o
    const int base = (tid & 31) & ~3;
    const int gidx = k * Hdim + q;

    if (cta < Bsz) {
        // ------------------------------ layer 0 (producer) ------------------------
        __shared__ __align__(16) float h_sh[2][Hdim];
        const int b = cta;

        unsigned long long wp[Hdim / 2];
#pragma unroll
        for (int j = 0; j < Hdim / 2; j++) {
            float2 v = *reinterpret_cast<const float2*>(Whh0 + gidx * Hdim + 2 * j);
            wp[j] = pack2v(v.x, v.y);
        }

        if (tid < Hdim) { h_sh[0][tid] = 0.0f; h_sh[1][tid] = 0.0f; }
        __syncthreads();

        const float* xp = xproj + (size_t)b * Tlen * Gdim;
        float xcur = xp[gidx];
        float c = 0.0f;

        for (int t = 0; t < Tlen; t++) {
            float xnext = (t + 1 < Tlen) ? xp[(size_t)(t + 1) * Gdim + gidx] : 0.0f;
            float val = xcur + dot64(wp, h_sh[t & 1]);
            xcur = xnext;

            float act = (k == 2) ? tanh_fast(val) : sigmoidf_(val);
            float iv = __shfl_sync(0xffffffffu, act, base + 0);
            float fv = __shfl_sync(0xffffffffu, act, base + 1);
            float gv = __shfl_sync(0xffffffffu, act, base + 2);
            float ov = __shfl_sync(0xffffffffu, act, base + 3);

            c = fv * c + iv * gv;
            float hn = ov * tanh_fast(c);

            if (k == 0) {
                h_sh[(t + 1) & 1][q] = hn;
                h0g[((size_t)b * Tlen + t) * Hdim + q] = hn;
            }
            __syncthreads();
            if (((t + 1) & 15) == 0 && tid == 0) {
                __threadfence();
                asm volatile("st.release.gpu.global.u32 [%0], %1;"
                             :: "l"(&g_flag[b * 32]), "r"(t + 1) : "memory");
            }
        }
    } else {
        // ------------------------------ layer 1 (consumer) ------------------------
        __shared__ __align__(16) float h0s[2][Hdim];
        __shared__ __align__(16) float h1s[2][Hdim];
        const int b = cta - Bsz;
        const int* fl = &g_flag[b * 32];

        unsigned long long wih[Hdim / 2], whh[Hdim / 2];
#pragma unroll
        for (int j = 0; j < Hdim / 2; j++) {
            float2 vi = *reinterpret_cast<const float2*>(Wih1 + gidx * Hdim + 2 * j);
            float2 vh = *reinterpret_cast<const float2*>(Whh1 + gidx * Hdim + 2 * j);
            wih[j] = pack2v(vi.x, vi.y);
            whh[j] = pack2v(vh.x, vh.y);
        }
        const float bias = bih1[gidx] + bhh1[gidx];

        if (tid < Hdim) { h1s[0][tid] = 0.0f; h1s[1][tid] = 0.0f; }

        const float* h0row = h0g + (size_t)b * Tlen * Hdim;
        float rnext = 0.0f;
        if (k == 1) {                 // prefetch threads (one per h index)
            wait_flag(fl, 1);         // chunk 0 done (flag jumps to >=16)
            h0s[0][q] = h0row[q];     // h0[0]
            rnext = h0row[Hdim + q];  // h0[1] into register
        }
        __syncthreads();

        float c = 0.0f;
        for (int t = 0; t < Tlen; t++) {
            if (k == 1) {
                if (t + 1 < Tlen) h0s[(t + 1) & 1][q] = rnext;     // stage h0[t+1]
                if (t + 2 < Tlen) {
                    wait_flag(fl, t + 3);                          // chunk of t+2 done
                    rnext = h0row[(size_t)(t + 2) * Hdim + q];     // load h0[t+2]
                }
            }
            float val = bias + dot64(wih, h0s[t & 1]) + dot64(whh, h1s[t & 1]);

            float act = (k == 2) ? tanh_fast(val) : sigmoidf_(val);
            float iv = __shfl_sync(0xffffffffu, act, base + 0);
            float fv = __shfl_sync(0xffffffffu, act, base + 1);
            float gv = __shfl_sync(0xffffffffu, act, base + 2);
            float ov = __shfl_sync(0xffffffffu, act, base + 3);

            c = fv * c + iv * gv;
            float hn = ov * tanh_fast(c);

            if (k == 0) {
                h1s[(t + 1) & 1][q] = hn;
                ah_out[((size_t)b * Tlen + t) * Hdim + q] = __float2half(hn);
            }
            __syncthreads();
        }
    }
}

// ---------------- Wl -> fp16 (scaled by 8 for fp16 normal range) -------
__global__ void cvt_bh(const float* __restrict__ in, __half* __restrict__ out, int n)
{
    int i = blockIdx.x * blockDim.x + threadIdx.x;
    if (i < n) out[i] = __float2half(in[i] * 8.0f);
}

// ============ HMMA fp16 logits GEMM (byte-identical to passing R7) ==================
#define SWZ128(off) ((off) ^ (((off) >> 3) & 0x70))
#define LS_B    0
#define LS_A    8192
#define LS_ASTG 16384
#define LG_SMEM (8192 + 2 * 16384 + 1024)
#define NM_TILES 8

static __device__ __forceinline__ uint32_t smem_u32(const void* p) {
    uint32_t a;
    asm("{ .reg .u64 t; cvta.to.shared.u64 t, %1; cvt.u32.u64 %0, t; }"
        : "=r"(a) : "l"(p));
    return a;
}
__device__ __forceinline__ void cp16(uint32_t dst, const void* src) {
    asm volatile("cp.async.cg.shared.global [%0], [%1], 16;"
                 :: "r"(dst), "l"(src));
}
__device__ __forceinline__ void cp_commit() {
    asm volatile("cp.async.commit_group;" ::: "memory");
}
template <int N>
__device__ __forceinline__ void cp_wait() {
    asm volatile("cp.async.wait_group %0;" :: "n"(N) : "memory");
}
__device__ __forceinline__ void ldsm_x4(uint32_t& r0, uint32_t& r1, uint32_t& r2,
                                        uint32_t& r3, uint32_t addr) {
    asm volatile("ldmatrix.sync.aligned.m8n8.x4.shared.b16 {%0,%1,%2,%3}, [%4];"
                 : "=r"(r0), "=r"(r1), "=r"(r2), "=r"(r3) : "r"(addr));
}
__device__ __forceinline__ void mma_f16(float* c, uint32_t a0, uint32_t a1,
                                        uint32_t a2, uint32_t a3,
                                        uint32_t b0, uint32_t b1) {
    asm volatile("mma.sync.aligned.m16n8k16.row.col.f32.f16.f16.f32 "
                 "{%0,%1,%2,%3}, {%4,%5,%6,%7}, {%8,%9}, {%0,%1,%2,%3};"
                 : "+f"(c[0]), "+f"(c[1]), "+f"(c[2]), "+f"(c[3])
                 : "r"(a0), "r"(a1), "r"(a2), "r"(a3), "r"(b0), "r"(b1));
}
__device__ __forceinline__ void stg_cs_f2(float* p, float x, float y) {
    asm volatile("st.global.cs.v2.f32 [%0], {%1,%2};" :: "l"(p), "f"(x), "f"(y));
}

__device__ __forceinline__ void load_A_stage(uint32_t sA, const __half* Ah,
                                             int bm, int tid) {
    const int row = tid >> 1;
    const int cb = (tid & 1) * 4;
    const char* src = reinterpret_cast<const char*>(Ah + (size_t)(bm + row) * Hdim);
#pragma unroll
    for (int i = 0; i < 4; i++) {
        uint32_t off = SWZ128((uint32_t)(row * 128 + (cb + i) * 16));
        cp16(sA + off, src + (cb + i) * 16);
    }
}

__global__ void __launch_bounds__(256)
logits_gemm(const __half* __restrict__ Ah, const __half* __restrict__ Bh,
            const float* __restrict__ bias, float* __restrict__ C)
{
    extern __shared__ char smem_raw[];
    const uint32_t sb0 = smem_u32(smem_raw);
    const uint32_t sb = (sb0 + 1023) & ~1023u;

    const int tid = threadIdx.x;
    const int lane = tid & 31;
    const int wid = tid >> 5;
    const int wm = wid & 3;
    const int wn = wid >> 2;
    const int bn = blockIdx.x * 64;
    const int bm0 = blockIdx.y * (NM_TILES * 128);

    {
        const int row = tid >> 2;
        const int cb = (tid & 3) * 2;
        const char* src = reinterpret_cast<const char*>(Bh + (size_t)(bn + row) * Hdim);
#pragma unroll
        for (int i = 0; i < 2; i++) {
            uint32_t off = SWZ128((uint32_t)(row * 128 + (cb + i) * 16));
            cp16(sb + LS_B + off, src + (cb + i) * 16);
        }
    }
    load_A_stage(sb + LS_A, Ah, bm0, tid);
    cp_commit();

    const int gid = lane >> 2;
    const int tig = lane & 3;
    float2 bv[4];
#pragma unroll
    for (int nt = 0; nt < 4; nt++)
        bv[nt] = *reinterpret_cast<const float2*>(bias + bn + wn * 32 + nt * 8 + 2 * tig);

    const int rsel = lane & 15;
    const int csel = lane >> 4;

    for (int it = 0; it < NM_TILES; it++) {
        const uint32_t sA = sb + LS_A + (it & 1) * LS_ASTG;
        if (it + 1 < NM_TILES) {
            load_A_stage(sb + LS_A + ((it + 1) & 1) * LS_ASTG, Ah,
                         bm0 + (it + 1) * 128, tid);
            cp_commit();
            cp_wait<1>();
        } else {
            cp_wait<0>();
        }
        __syncthreads();

        float acc[2][4][4];
#pragma unroll
        for (int i = 0; i < 2; i++)
#pragma unroll
            for (int j = 0; j < 4; j++)
#pragma unroll
                for (int q = 0; q < 4; q++) acc[i][j][q] = 0.0f;

#pragma unroll
        for (int ks = 0; ks < 4; ks++) {
            const int col16 = ks * 2 + csel;
            uint32_t a[2][4];
#pragma unroll
            for (int mt = 0; mt < 2; mt++) {
                int row = wm * 32 + mt * 16 + rsel;
                uint32_t addr = sA + SWZ128((uint32_t)(row * 128 + col16 * 16));
                ldsm_x4(a[mt][0], a[mt][1], a[mt][2], a[mt][3], addr);
            }
            uint32_t b0[4], b1[4];
#pragma unroll
            for (int np = 0; np < 2; np++) {
                int row = wn * 32 + np * 16 + rsel;
                uint32_t addr = sb + LS_B + SWZ128((uint32_t)(row * 128 + col16 * 16));
                uint32_t r0, r1, r2, r3;
                ldsm_x4(r0, r1, r2, r3, addr);
                b0[np * 2 + 0] = r0; b0[np * 2 + 1] = r1;
                b1[np * 2 + 0] = r2; b1[np * 2 + 1] = r3;
            }
#pragma unroll
            for (int mt = 0; mt < 2; mt++)
#pragma unroll
                for (int nt = 0; nt < 4; nt++)
                    mma_f16(acc[mt][nt], a[mt][0], a[mt][1], a[mt][2], a[mt][3],
                            b0[nt], b1[nt]);
        }

        const int bm = bm0 + it * 128;
#pragma unroll
        for (int nt = 0; nt < 4; nt++) {
            const int gn = bn + wn * 32 + nt * 8 + 2 * tig;
#pragma unroll
            for (int mt = 0; mt < 2; mt++) {
                const int gm0 = bm + wm * 32 + mt * 16 + gid;
                float x0 = fmaf(acc[mt][nt][0], 0.125f, bv[nt].x);
                float y0 = fmaf(acc[mt][nt][1], 0.125f, bv[nt].y);
                float x1 = fmaf(acc[mt][nt][2], 0.125f, bv[nt].x);
                float y1 = fmaf(acc[mt][nt][3], 0.125f, bv[nt].y);
                stg_cs_f2(C + (size_t)gm0 * Vocab + gn, x0, y0);
                stg_cs_f2(C + (size_t)(gm0 + 8) * Vocab + gn, x1, y1);
            }
        }
        __syncthreads();
    }
}

// ------------------------------------ launch --------------------------------------
extern "C" void kernel_launch(void* const* d_in, const int* in_sizes, int n_in,
                              void* d_out, int out_size)
{
    (void)in_sizes; (void)n_in; (void)out_size;
    const float* x     = (const float*)d_in[0];
    const float* W_ih0 = (const float*)d_in[1];
    const float* W_hh0 = (const float*)d_in[2];
    const float* b_ih0 = (const float*)d_in[3];
    const float* b_hh0 = (const float*)d_in[4];
    const float* W_ih1 = (const float*)d_in[5];
    const float* W_hh1 = (const float*)d_in[6];
    const float* b_ih1 = (const float*)d_in[7];
    const float* b_hh1 = (const float*)d_in[8];
    const float* Wl    = (const float*)d_in[9];
    const float* bl    = (const float*)d_in[10];
    float* out = (float*)d_out;

    void* p;
    cudaGetSymbolAddress(&p, g_xproj); float* xproj = (float*)p;
    cudaGetSymbolAddress(&p, g_h0);    float* h0g   = (float*)p;
    cudaGetSymbolAddress(&p, g_Ah);    __half* Ah   = (__half*)p;
    cudaGetSymbolAddress(&p, g_Bh);    __half* Bh   = (__half*)p;

    // flag reset must precede lstm_chain on every replay
    reset_flags<<<1, Bsz>>>();

    // Wl -> fp16 (independent of LSTM chain)
    cvt_bh<<<(Vocab * Hdim + 255) / 256, 256>>>(Wl, Bh, Vocab * Hdim);

    // Layer 0 input projection (biases folded in)
    gemm_nt_bias<<<dim3(Gdim / 64, Mrows / 64), 256>>>(
        x, W_ih0, b_ih0, b_hh0, xproj, Mrows, Gdim, INSZ);

    // Both recurrences, chunk-pipelined across CTAs (proj1 folded into consumer)
    lstm_chain<<<2 * Bsz, 256>>>(xproj, W_hh0, W_ih1, W_hh1, b_ih1, b_hh1, h0g, Ah);

    // Logits via pipelined HMMA fp16 single pass
    cudaFuncSetAttribute(logits_gemm, cudaFuncAttributeMaxDynamicSharedMemorySize, LG_SMEM);
    logits_gemm<<<dim3(Vocab / 64, Mrows / (NM_TILES * 128)), 256, LG_SMEM>>>(
        Ah, Bh, bl, out);
}

// round 12
// speedup vs baseline: 1.1192x; 1.0563x over previous
#include <cuda_runtime.h>
#include <cuda_fp16.h>
#include <cstdint>

// Problem constants
#define Bsz   64
#define Tlen  256
#define INSZ  256
#define Hdim  64
#define Gdim  256        // 4*Hdim
#define Vocab 8000
#define Mrows (Bsz * Tlen)   // 16384

// Scratch (device globals; no allocation allowed in kernel_launch)
__device__ float g_xproj[Mrows * Gdim];
__device__ float g_h1[Mrows * Hdim];
__device__ __align__(128) __half g_Ah[Mrows * Hdim];    // h2 rounded to fp16
__device__ __align__(128) __half g_Bh[Vocab * Hdim];    // 8*Wl rounded to fp16

// ---------------- packed f32x2 helpers ----------------
__device__ __forceinline__ unsigned long long pack2(float x) {
    unsigned long long r;
    asm("mov.b64 %0, {%1, %1};" : "=l"(r) : "f"(x));
    return r;
}
__device__ __forceinline__ unsigned long long pack2v(float x, float y) {
    unsigned long long r;
    asm("mov.b64 %0, {%1, %2};" : "=l"(r) : "f"(x), "f"(y));
    return r;
}
__device__ __forceinline__ void fma2(unsigned long long& d, unsigned long long a,
                                     unsigned long long b) {
    asm("fma.rn.f32x2 %0, %1, %2, %0;" : "+l"(d) : "l"(a), "l"(b));
}
__device__ __forceinline__ float2 unpack2(unsigned long long v) {
    float2 f;
    asm("mov.b64 {%0, %1}, %2;" : "=f"(f.x), "=f"(f.y) : "l"(v));
    return f;
}
__device__ __forceinline__ float fast_rcp(float x) {
    float r;
    asm("rcp.approx.f32 %0, %1;" : "=f"(r) : "f"(x));
    return r;
}
__device__ __forceinline__ float sigmoidf_(float x) {
    return fast_rcp(1.0f + __expf(-x));
}
__device__ __forceinline__ float tanh_fast(float x) {
    return 1.0f - 2.0f * fast_rcp(1.0f + __expf(2.0f * x));
}
// 64-long dot via LDS.128: wp = 32 packed f32x2, h = 64 floats (16B-aligned SMEM).
// 16 LDS.128 instead of 32 LDS.64 — halves the shared-load issue count.
__device__ __forceinline__ float dot64v(const unsigned long long* wp, const float* h) {
    const ulonglong2* hp = reinterpret_cast<const ulonglong2*>(h);
    unsigned long long a0 = 0ULL, a1 = 0ULL, a2 = 0ULL, a3 = 0ULL;
#pragma unroll
    for (int j = 0; j < 16; j += 2) {
        ulonglong2 h01 = hp[j];
        ulonglong2 h23 = hp[j + 1];
        fma2(a0, wp[2 * j + 0], h01.x);
        fma2(a1, wp[2 * j + 1], h01.y);
        fma2(a2, wp[2 * j + 2], h23.x);
        fma2(a3, wp[2 * j + 3], h23.y);
    }
    float2 s0 = unpack2(a0), s1 = unpack2(a1), s2 = unpack2(a2), s3 = unpack2(a3);
    return (((s0.x + s0.y) + (s1.x + s1.y)) + ((s2.x + s2.y) + (s3.x + s3.y)));
}

// ---------------- generic C[M,N] = A[M,K] * B[N,K]^T + bias1 (+bias2) ----------------
__global__ void gemm_nt_bias(const float* __restrict__ A, const float* __restrict__ Bm,
                             const float* __restrict__ bias1, const float* __restrict__ bias2,
                             float* __restrict__ C, int M, int N, int K)
{
    __shared__ __align__(16) float As[64][17];
    __shared__ __align__(16) float Bs[16][68];

    const int t  = threadIdx.x;
    const int bm = blockIdx.y * 64;
    const int bn = blockIdx.x * 64;
    const int tm = (t >> 4) << 2;
    const int tn = (t & 15) << 2;
    const int lr = t >> 2;
    const int lk = (t & 3) << 2;

    unsigned long long acc[4][2];
#pragma unroll
    for (int i = 0; i < 4; i++) { acc[i][0] = 0ULL; acc[i][1] = 0ULL; }

    const float* Aptr = A  + (size_t)(bm + lr) * K + lk;
    const float* Bptr = Bm + (size_t)(bn + lr) * K + lk;

    for (int k0 = 0; k0 < K; k0 += 16) {
        float4 av = *reinterpret_cast<const float4*>(Aptr + k0);
        float4 bv = *reinterpret_cast<const float4*>(Bptr + k0);
        As[lr][lk + 0] = av.x; As[lr][lk + 1] = av.y;
        As[lr][lk + 2] = av.z; As[lr][lk + 3] = av.w;
        Bs[lk + 0][lr] = bv.x; Bs[lk + 1][lr] = bv.y;
        Bs[lk + 2][lr] = bv.z; Bs[lk + 3][lr] = bv.w;
        __syncthreads();
#pragma unroll
        for (int kk = 0; kk < 16; kk++) {
            unsigned long long b0 =
                *reinterpret_cast<const unsigned long long*>(&Bs[kk][tn]);
            unsigned long long b1 =
                *reinterpret_cast<const unsigned long long*>(&Bs[kk][tn + 2]);
#pragma unroll
            for (int i = 0; i < 4; i++) {
                unsigned long long ap = pack2(As[tm + i][kk]);
                fma2(acc[i][0], ap, b0);
                fma2(acc[i][1], ap, b1);
            }
        }
        __syncthreads();
    }

    float4 bvec;
    bvec.x = bias1[bn + tn + 0];
    bvec.y = bias1[bn + tn + 1];
    bvec.z = bias1[bn + tn + 2];
    bvec.w = bias1[bn + tn + 3];
    if (bias2) {
        bvec.x += bias2[bn + tn + 0];
        bvec.y += bias2[bn + tn + 1];
        bvec.z += bias2[bn + tn + 2];
        bvec.w += bias2[bn + tn + 3];
    }
#pragma unroll
    for (int i = 0; i < 4; i++) {
        float2 lo = unpack2(acc[i][0]);
        float2 hi = unpack2(acc[i][1]);
        float4 v = make_float4(lo.x + bvec.x, lo.y + bvec.y,
                               hi.x + bvec.z, hi.y + bvec.w);
        *reinterpret_cast<float4*>(&C[(size_t)(bm + tm + i) * N + bn + tn]) = v;
    }
}

// ============ LSTM recurrence: quad-shuffle, one barrier, LDS.128 dot ===============
__global__ void __launch_bounds__(256, 1)
lstm_layer(const float* __restrict__ xproj,   // [B,T,256] incl. biases
           const float* __restrict__ Whh,     // [256,64]
           float* __restrict__ hout,          // [B,T,64] fp32 or null
           __half* __restrict__ ah_out)       // [B,T,64] fp16 or null
{
    __shared__ __align__(16) float h_sh[2][Hdim];

    const int b = blockIdx.x;
    const int tid = threadIdx.x;
    const int q = tid >> 2;          // h index 0..63
    const int k = tid & 3;           // gate type 0=i 1=f 2=g 3=o
    const int base = (tid & 31) & ~3;
    const int gidx = k * Hdim + q;   // weight row / xproj column

    unsigned long long wp[Hdim / 2];
#pragma unroll
    for (int j = 0; j < Hdim / 2; j++) {
        float2 v = *reinterpret_cast<const float2*>(Whh + gidx * Hdim + 2 * j);
        wp[j] = pack2v(v.x, v.y);
    }

    if (tid < Hdim) { h_sh[0][tid] = 0.0f; h_sh[1][tid] = 0.0f; }
    __syncthreads();

    const float* xp = xproj + (size_t)b * Tlen * Gdim;
    float xcur = xp[gidx];
    float c = 0.0f;

    for (int t = 0; t < Tlen; t++) {
        float xnext = (t + 1 < Tlen) ? xp[(size_t)(t + 1) * Gdim + gidx] : 0.0f;
        float val = xcur + dot64v(wp, h_sh[t & 1]);
        xcur = xnext;

        float act = (k == 2) ? tanh_fast(val) : sigmoidf_(val);

        float iv = __shfl_sync(0xffffffffu, act, base + 0);
        float fv = __shfl_sync(0xffffffffu, act, base + 1);
        float gv = __shfl_sync(0xffffffffu, act, base + 2);
        float ov = __shfl_sync(0xffffffffu, act, base + 3);

        c = fv * c + iv * gv;
        float hn = ov * tanh_fast(c);

        if (k == 0) {
            h_sh[(t + 1) & 1][q] = hn;
            size_t idx = ((size_t)b * Tlen + t) * Hdim + q;
            if (hout) hout[idx] = hn;
            if (ah_out) ah_out[idx] = __float2half(hn);
        }
        __syncthreads();
    }
}

// ---------------- Wl -> fp16 (scaled by 8 for fp16 normal range) -------
__global__ void cvt_bh(const float* __restrict__ in, __half* __restrict__ out, int n)
{
    int i = blockIdx.x * blockDim.x + threadIdx.x;
    if (i < n) out[i] = __float2half(in[i] * 8.0f);
}

// ============ HMMA fp16 logits GEMM (R7 structure, occupancy hint 3) ================
#define SWZ128(off) ((off) ^ (((off) >> 3) & 0x70))
#define LS_B    0
#define LS_A    8192
#define LS_ASTG 16384
#define LG_SMEM (8192 + 2 * 16384 + 1024)
#define NM_TILES 8

static __device__ __forceinline__ uint32_t smem_u32(const void* p) {
    uint32_t a;
    asm("{ .reg .u64 t; cvta.to.shared.u64 t, %1; cvt.u32.u64 %0, t; }"
        : "=r"(a) : "l"(p));
    return a;
}
__device__ __forceinline__ void cp16(uint32_t dst, const void* src) {
    asm volatile("cp.async.cg.shared.global [%0], [%1], 16;"
                 :: "r"(dst), "l"(src));
}
__device__ __forceinline__ void cp_commit() {
    asm volatile("cp.async.commit_group;" ::: "memory");
}
template <int N>
__device__ __forceinline__ void cp_wait() {
    asm volatile("cp.async.wait_group %0;" :: "n"(N) : "memory");
}
__device__ __forceinline__ void ldsm_x4(uint32_t& r0, uint32_t& r1, uint32_t& r2,
                                        uint32_t& r3, uint32_t addr) {
    asm volatile("ldmatrix.sync.aligned.m8n8.x4.shared.b16 {%0,%1,%2,%3}, [%4];"
                 : "=r"(r0), "=r"(r1), "=r"(r2), "=r"(r3) : "r"(addr));
}
__device__ __forceinline__ void mma_f16(float* c, uint32_t a0, uint32_t a1,
                                        uint32_t a2, uint32_t a3,
                                        uint32_t b0, uint32_t b1) {
    asm volatile("mma.sync.aligned.m16n8k16.row.col.f32.f16.f16.f32 "
                 "{%0,%1,%2,%3}, {%4,%5,%6,%7}, {%8,%9}, {%0,%1,%2,%3};"
                 : "+f"(c[0]), "+f"(c[1]), "+f"(c[2]), "+f"(c[3])
                 : "r"(a0), "r"(a1), "r"(a2), "r"(a3), "r"(b0), "r"(b1));
}
__device__ __forceinline__ void stg_cs_f2(float* p, float x, float y) {
    asm volatile("st.global.cs.v2.f32 [%0], {%1,%2};" :: "l"(p), "f"(x), "f"(y));
}

__device__ __forceinline__ void load_A_stage(uint32_t sA, const __half* Ah,
                                             int bm, int tid) {
    const int row = tid >> 1;
    const int cb = (tid & 1) * 4;
    const char* src = reinterpret_cast<const char*>(Ah + (size_t)(bm + row) * Hdim);
#pragma unroll
    for (int i = 0; i < 4; i++) {
        uint32_t off = SWZ128((uint32_t)(row * 128 + (cb + i) * 16));
        cp16(sA + off, src + (cb + i) * 16);
    }
}

__global__ void __launch_bounds__(256, 3)
logits_gemm(const __half* __restrict__ Ah, const __half* __restrict__ Bh,
            const float* __restrict__ bias, float* __restrict__ C)
{
    extern __shared__ char smem_raw[];
    const uint32_t sb0 = smem_u32(smem_raw);
    const uint32_t sb = (sb0 + 1023) & ~1023u;

    const int tid = threadIdx.x;
    const int lane = tid & 31;
    const int wid = tid >> 5;
    const int wm = wid & 3;
    const int wn = wid >> 2;
    const int bn = blockIdx.x * 64;
    const int bm0 = blockIdx.y * (NM_TILES * 128);

    {
        const int row = tid >> 2;
        const int cb = (tid & 3) * 2;
        const char* src = reinterpret_cast<const char*>(Bh + (size_t)(bn + row) * Hdim);
#pragma unroll
        for (int i = 0; i < 2; i++) {
            uint32_t off = SWZ128((uint32_t)(row * 128 + (cb + i) * 16));
            cp16(sb + LS_B + off, src + (cb + i) * 16);
        }
    }
    load_A_stage(sb + LS_A, Ah, bm0, tid);
    cp_commit();

    const int gid = lane >> 2;
    const int tig = lane & 3;
    float2 bv[4];
#pragma unroll
    for (int nt = 0; nt < 4; nt++)
        bv[nt] = *reinterpret_cast<const float2*>(bias + bn + wn * 32 + nt * 8 + 2 * tig);

    const int rsel = lane & 15;
    const int csel = lane >> 4;

    for (int it = 0; it < NM_TILES; it++) {
        const uint32_t sA = sb + LS_A + (it & 1) * LS_ASTG;
        if (it + 1 < NM_TILES) {
            load_A_stage(sb + LS_A + ((it + 1) & 1) * LS_ASTG, Ah,
                         bm0 + (it + 1) * 128, tid);
            cp_commit();
            cp_wait<1>();
        } else {
            cp_wait<0>();
        }
        __syncthreads();

        float acc[2][4][4];
#pragma unroll
        for (int i = 0; i < 2; i++)
#pragma unroll
            for (int j = 0; j < 4; j++)
#pragma unroll
                for (int q = 0; q < 4; q++) acc[i][j][q] = 0.0f;

#pragma unroll
        for (int ks = 0; ks < 4; ks++) {
            const int col16 = ks * 2 + csel;
            uint32_t a[2][4];
#pragma unroll
            for (int mt = 0; mt < 2; mt++) {
                int row = wm * 32 + mt * 16 + rsel;
                uint32_t addr = sA + SWZ128((uint32_t)(row * 128 + col16 * 16));
                ldsm_x4(a[mt][0], a[mt][1], a[mt][2], a[mt][3], addr);
            }
            uint32_t b0[4], b1[4];
#pragma unroll
            for (int np = 0; np < 2; np++) {
                int row = wn * 32 + np * 16 + rsel;
                uint32_t addr = sb + LS_B + SWZ128((uint32_t)(row * 128 + col16 * 16));
                uint32_t r0, r1, r2, r3;
                ldsm_x4(r0, r1, r2, r3, addr);
                b0[np * 2 + 0] = r0; b0[np * 2 + 1] = r1;
                b1[np * 2 + 0] = r2; b1[np * 2 + 1] = r3;
            }
#pragma unroll
            for (int mt = 0; mt < 2; mt++)
#pragma unroll
                for (int nt = 0; nt < 4; nt++)
                    mma_f16(acc[mt][nt], a[mt][0], a[mt][1], a[mt][2], a[mt][3],
                            b0[nt], b1[nt]);
        }

        const int bm = bm0 + it * 128;
#pragma unroll
        for (int nt = 0; nt < 4; nt++) {
            const int gn = bn + wn * 32 + nt * 8 + 2 * tig;
#pragma unroll
            for (int mt = 0; mt < 2; mt++) {
                const int gm0 = bm + wm * 32 + mt * 16 + gid;
                float x0 = fmaf(acc[mt][nt][0], 0.125f, bv[nt].x);
                float y0 = fmaf(acc[mt][nt][1], 0.125f, bv[nt].y);
                float x1 = fmaf(acc[mt][nt][2], 0.125f, bv[nt].x);
                float y1 = fmaf(acc[mt][nt][3], 0.125f, bv[nt].y);
                stg_cs_f2(C + (size_t)gm0 * Vocab + gn, x0, y0);
                stg_cs_f2(C + (size_t)(gm0 + 8) * Vocab + gn, x1, y1);
            }
        }
        __syncthreads();
    }
}

// ------------------------------------ launch --------------------------------------
extern "C" void kernel_launch(void* const* d_in, const int* in_sizes, int n_in,
                              void* d_out, int out_size)
{
    (void)in_sizes; (void)n_in; (void)out_size;
    const float* x     = (const float*)d_in[0];
    const float* W_ih0 = (const float*)d_in[1];
    const float* W_hh0 = (const float*)d_in[2];
    const float* b_ih0 = (const float*)d_in[3];
    const float* b_hh0 = (const float*)d_in[4];
    const float* W_ih1 = (const float*)d_in[5];
    const float* W_hh1 = (const float*)d_in[6];
    const float* b_ih1 = (const float*)d_in[7];
    const float* b_hh1 = (const float*)d_in[8];
    const float* Wl    = (const float*)d_in[9];
    const float* bl    = (const float*)d_in[10];
    float* out = (float*)d_out;

    void* p;
    cudaGetSymbolAddress(&p, g_xproj); float* xproj = (float*)p;
    cudaGetSymbolAddress(&p, g_h1);    float* h1    = (float*)p;
    cudaGetSymbolAddress(&p, g_Ah);    __half* Ah   = (__half*)p;
    cudaGetSymbolAddress(&p, g_Bh);    __half* Bh   = (__half*)p;

    // Wl -> fp16 (independent of LSTM chain)
    cvt_bh<<<(Vocab * Hdim + 255) / 256, 256>>>(Wl, Bh, Vocab * Hdim);

    // Layer 0 input projection
    gemm_nt_bias<<<dim3(Gdim / 64, Mrows / 64), 256>>>(
        x, W_ih0, b_ih0, b_hh0, xproj, Mrows, Gdim, INSZ);
    // Layer 0 recurrence -> h1 (fp32)
    lstm_layer<<<Bsz, Gdim>>>(xproj, W_hh0, h1, nullptr);
    // Layer 1 input projection
    gemm_nt_bias<<<dim3(Gdim / 64, Mrows / 64), 256>>>(
        h1, W_ih1, b_ih1, b_hh1, xproj, Mrows, Gdim, Hdim);
    // Layer 1 recurrence -> fp16 A directly
    lstm_layer<<<Bsz, Gdim>>>(xproj, W_hh1, nullptr, Ah);

    // Logits via pipelined HMMA fp16 single pass
    cudaFuncSetAttribute(logits_gemm, cudaFuncAttributeMaxDynamicSharedMemorySize, LG_SMEM);
    logits_gemm<<<dim3(Vocab / 64, Mrows / (NM_TILES * 128)), 256, LG_SMEM>>>(
        Ah, Bh, bl, out);
}